// round 10
// baseline (speedup 1.0000x reference)
#include <cuda_runtime.h>
#include <cuda_fp16.h>
#include <math.h>

#define B_TOT   131072
#define NN      17
#define H       32
#define EPS     1e-5f
#define D_IN    53
#define WPB     8           // warps per block (pass1)
#define SPW     8           // samples per warp (pass1)

// ---------------- scratch (device globals; no allocation allowed) ------------
__device__ __half gH2h[(size_t)B_TOT * NN * H];   // 142 MB fp16 staging of h2
__device__ float gSum[NN];    // zero at start of every run (finalize re-zeroes)
__device__ float gSq[NN];
__device__ float gA[NN];     // gamma*rsqrt(var+eps)/17
__device__ float gCbar;      // sum_n (beta - mean*A)/17

// ---------------- packed f32x2 helpers ---------------------------------------
typedef unsigned long long ull;

__device__ __forceinline__ ull pk2(float lo, float hi) {
    ull r; asm("mov.b64 %0,{%1,%2};" : "=l"(r) : "f"(lo), "f"(hi)); return r;
}
__device__ __forceinline__ void upk2(ull v, float& lo, float& hi) {
    asm("mov.b64 {%0,%1},%2;" : "=f"(lo), "=f"(hi) : "l"(v));
}
__device__ __forceinline__ void ffma2(ull& d, ull a, ull b) {
    asm("fma.rn.f32x2 %0,%1,%2,%0;" : "+l"(d) : "l"(a), "l"(b));
}
// extract element n (0..15) from pack array; n is compile-time constant at use
__device__ __forceinline__ float getp(const ull* p, int n) {
    float lo, hi; upk2(p[n >> 1], lo, hi);
    return (n & 1) ? hi : lo;
}

__device__ __forceinline__ float elu_f(float x) {
    return fmaxf(x, 0.f) + (__expf(fminf(x, 0.f)) - 1.f);
}

// ---------------- cp.async helpers -------------------------------------------
__device__ __forceinline__ void cp_async4(unsigned dst, const float* src) {
    asm volatile("cp.async.ca.shared.global [%0], [%1], 4;" :: "r"(dst), "l"(src));
}
__device__ __forceinline__ void cp_commit() {
    asm volatile("cp.async.commit_group;" ::: "memory");
}
__device__ __forceinline__ void cp_wait0() {
    asm volatile("cp.async.wait_group 0;" ::: "memory");
}

// ---------------------------------------------------------------------------
// Pass 1: per-sample 2-layer GCN, h2 -> gH2h (fp16). Two samples processed
// concurrently per warp (A/B) to double independent work between syncs.
#define P1_ADJ   0
#define P1_X     (P1_ADJ + WPB*4*NN*20)
#define P1_BUF   (P1_X   + WPB*4*20)
#define P1_D     (P1_BUF + WPB*2*NN*36)
#define P1_DX    (P1_D   + WPB*2*20)
#define P1_SS    (P1_DX  + WPB*2*20)
#define P1_FLOATS (P1_SS + WPB*2*20)

__global__ __launch_bounds__(256, 2) void pass1_kernel(
    const float* __restrict__ x_str,   // [B,17,1]
    const float* __restrict__ adj,     // [B,17,17]
    const float* __restrict__ W1,      // [1,32]
    const float* __restrict__ b1,      // [32]
    const float* __restrict__ W2,      // [32,32]
    const float* __restrict__ b2)      // [32]
{
    extern __shared__ float sm1[];

    const int tid  = threadIdx.x;
    const int lane = tid & 31;
    const int w    = tid >> 5;

    float* adjW = sm1 + P1_ADJ + w * (4 * NN * 20);
    float* xW   = sm1 + P1_X   + w * (4 * 20);
    float* bufA = sm1 + P1_BUF + w * (2 * NN * 36);
    float* bufB = bufA + NN * 36;
    float* dA   = sm1 + P1_D   + w * 40;
    float* dB   = dA + 20;
    float* dxA  = sm1 + P1_DX  + w * 40;
    float* dxB  = dxA + 20;
    float* ssA  = sm1 + P1_SS  + w * 40;
    float* ssB  = ssA + 20;

    const float w1l = W1[lane];
    const float b1l = b1[lane];
    const float b2l = b2[lane];

    ull W2p[16];
    #pragma unroll
    for (int j = 0; j < 16; j++)
        W2p[j] = pk2(W2[(2 * j) * H + lane], W2[(2 * j + 1) * H + lane]);

    const long base = ((long)blockIdx.x * WPB + w) * SPW;

    // issue async loads of sample b into rotating buffer bf (0..3)
    auto issue = [&](long b, int bf) {
        const float* adjp = adj + b * (NN * NN);
        const unsigned ab = (unsigned)__cvta_generic_to_shared(adjW + bf * (NN * 20));
        const unsigned xb = (unsigned)__cvta_generic_to_shared(xW + bf * 20);
        #pragma unroll
        for (int j = 0; j < 10; j++) {
            int idx = lane + 32 * j;
            if (idx < NN * NN) {
                int n = (idx * 3857) >> 16;         // idx/17 for idx<=288
                cp_async4(ab + (unsigned)(idx + 3 * n) * 4u, adjp + idx);
            }
        }
        if (lane < NN) cp_async4(xb + (unsigned)lane * 4u, x_str + b * NN + lane);
    };

    issue(base + 0, 0);
    issue(base + 1, 1);
    cp_commit();

    #pragma unroll 1
    for (int p = 0; p < SPW / 2; p++) {
        const long bA = base + 2 * p;
        const long bB = bA + 1;
        cp_wait0();
        __syncwarp();

        const float* curA = adjW + ((2 * p) & 3) * (NN * 20);
        const float* curB = adjW + ((2 * p + 1) & 3) * (NN * 20);
        const float* xA   = xW + ((2 * p) & 3) * 20;
        const float* xB   = xW + ((2 * p + 1) & 3) * 20;

        if (p + 1 < SPW / 2) {
            issue(bA + 2, (2 * p + 2) & 3);
            issue(bB + 2, (2 * p + 3) & 3);
            cp_commit();
        }

        // degrees of A_hat = adj + I ; dv = d^-1/2 ; dx = dv*x  (A and B)
        if (lane < NN) {
            float dgA = 1.0f, dgB = 1.0f;
            #pragma unroll
            for (int m = 0; m < NN; m++) {
                dgA += curA[lane * 20 + m];
                dgB += curB[lane * 20 + m];
            }
            float dvA = dgA > 0.f ? rsqrtf(dgA) : 0.f;
            float dvB = dgB > 0.f ? rsqrtf(dgB) : 0.f;
            dA[lane]  = dvA;  dxA[lane] = dvA * xA[lane];
            dB[lane]  = dvB;  dxB[lane] = dvB * xB[lane];
        }
        __syncwarp();

        // s[n] = dv[n] * ( sum_m A[n,m]*dx[m] + dx[n] )
        if (lane < NN) {
            float accA = 0.f, accB = 0.f;
            #pragma unroll
            for (int m = 0; m < NN; m++) {
                accA += curA[lane * 20 + m] * dxA[m];
                accB += curB[lane * 20 + m] * dxB[m];
            }
            ssA[lane] = dA[lane] * (accA + dxA[lane]);
            ssB[lane] = dB[lane] * (accB + dxB[lane]);
        }
        __syncwarp();

        // h1d[m] = elu(s[m]*w1 + b1) * dv[m], packed (this lane's channel)
        ull h1pA[8], h1pB[8];
        float h16A, h16B;
        {
            #pragma unroll
            for (int j = 0; j < 8; j++) {
                float a0 = elu_f(ssA[2 * j] * w1l + b1l) * dA[2 * j];
                float a1 = elu_f(ssA[2 * j + 1] * w1l + b1l) * dA[2 * j + 1];
                float c0 = elu_f(ssB[2 * j] * w1l + b1l) * dB[2 * j];
                float c1 = elu_f(ssB[2 * j + 1] * w1l + b1l) * dB[2 * j + 1];
                h1pA[j] = pk2(a0, a1);
                h1pB[j] = pk2(c0, c1);
            }
            h16A = elu_f(ssA[16] * w1l + b1l) * dA[16];
            h16B = elu_f(ssB[16] * w1l + b1l) * dB[16];
        }

        // agg[n] = dv[n] * ( sum_m A[n,m]*h1d[m] + h1d[n] )   (A and B)
        #pragma unroll
        for (int n = 0; n < NN; n++) {
            const ulonglong2* avA = reinterpret_cast<const ulonglong2*>(&curA[n * 20]);
            const ulonglong2* avB = reinterpret_cast<const ulonglong2*>(&curB[n * 20]);
            ull a0 = 0ull, a1 = 0ull, b0 = 0ull, b1v = 0ull;
            #pragma unroll
            for (int q = 0; q < 4; q++) {
                ulonglong2 vA = avA[q];
                ulonglong2 vB = avB[q];
                ffma2(a0,  vA.x, h1pA[2 * q]);
                ffma2(a1,  vA.y, h1pA[2 * q + 1]);
                ffma2(b0,  vB.x, h1pB[2 * q]);
                ffma2(b1v, vB.y, h1pB[2 * q + 1]);
            }
            float diagA = (n < 16) ? getp(h1pA, n) : h16A;
            float diagB = (n < 16) ? getp(h1pB, n) : h16B;
            float l0, h0, l1, h1;
            upk2(a0, l0, h0); upk2(a1, l1, h1);
            float accA = (l0 + h0) + (l1 + h1) + curA[n * 20 + 16] * h16A + diagA;
            upk2(b0, l0, h0); upk2(b1v, l1, h1);
            float accB = (l0 + h0) + (l1 + h1) + curB[n * 20 + 16] * h16B + diagB;
            bufA[n * 36 + lane] = accA * dA[n];
            bufB[n * 36 + lane] = accB * dB[n];
        }
        __syncwarp();

        // t = agg @ W2 + b2 ; h2 = elu(t) ; fp16 store  (A and B)
        __half* outA = gH2h + bA * (NN * H);
        __half* outB = gH2h + bB * (NN * H);
        #pragma unroll
        for (int n = 0; n < NN; n++) {
            const ulonglong2* bvA = reinterpret_cast<const ulonglong2*>(&bufA[n * 36]);
            const ulonglong2* bvB = reinterpret_cast<const ulonglong2*>(&bufB[n * 36]);
            ull a0 = 0ull, a1 = 0ull, b0 = 0ull, b1v = 0ull;
            #pragma unroll
            for (int q = 0; q < 8; q++) {
                ulonglong2 vA = bvA[q];
                ulonglong2 vB = bvB[q];
                ffma2(a0,  vA.x, W2p[2 * q]);
                ffma2(a1,  vA.y, W2p[2 * q + 1]);
                ffma2(b0,  vB.x, W2p[2 * q]);
                ffma2(b1v, vB.y, W2p[2 * q + 1]);
            }
            float l0, h0, l1, h1;
            upk2(a0, l0, h0); upk2(a1, l1, h1);
            outA[n * H + lane] = __float2half(elu_f((l0 + h0) + (l1 + h1) + b2l));
            upk2(b0, l0, h0); upk2(b1v, l1, h1);
            outB[n * H + lane] = __float2half(elu_f((l0 + h0) + (l1 + h1) + b2l));
        }
        __syncwarp();
    }
}

// ---------------------------------------------------------------------------
// Streaming BN-stats over gH2h. 272 threads: thread t owns half2 slot t of each
// sample (n = t/16). Coalesced warp reads; fp32 local accum then atomics.
// gSum/gSq are zero on entry: zero-initialized at load, re-zeroed by finalize.
__global__ __launch_bounds__(272) void stats_kernel() {
    __shared__ float sAcc[2 * NN];
    const int t = threadIdx.x;               // 0..271
    if (t < 2 * NN) sAcc[t] = 0.f;
    __syncthreads();

    const int n = t >> 4;
    const __half2* p = reinterpret_cast<const __half2*>(gH2h);
    float sum = 0.f, sq = 0.f;
    for (long b = blockIdx.x; b < B_TOT; b += gridDim.x) {
        float2 v = __half22float2(p[b * 272 + t]);
        sum += v.x + v.y;
        sq  += v.x * v.x + v.y * v.y;
    }
    atomicAdd(&sAcc[n], sum);
    atomicAdd(&sAcc[NN + n], sq);
    __syncthreads();
    if (t < NN)           atomicAdd(&gSum[t],      sAcc[t]);
    else if (t < 2 * NN)  atomicAdd(&gSq[t - NN],  sAcc[t]);
}

// ---------------------------------------------------------------------------
__global__ void finalize_kernel(const float* __restrict__ gamma,
                                const float* __restrict__ beta)
{
    int n = threadIdx.x;
    float Cl = 0.f;
    if (n < NN) {
        const float inv_cnt = 1.f / ((float)B_TOT * (float)H);
        float mean = gSum[n] * inv_cnt;
        float var  = gSq[n] * inv_cnt - mean * mean;
        float rs   = rsqrtf(var + EPS);
        float A    = gamma[n] * rs;
        float C    = beta[n] - mean * A;
        gA[n] = A * (1.f / 17.f);
        Cl    = C * (1.f / 17.f);
        // re-zero accumulators for the next run (replaces zero_stats kernel)
        gSum[n] = 0.f;
        gSq[n]  = 0.f;
    }
    #pragma unroll
    for (int off = 16; off; off >>= 1) Cl += __shfl_xor_sync(0xffffffffu, Cl, off);
    if (n == 0) gCbar = Cl;
}

// ---------------------------------------------------------------------------
// Pass 2: BN-fold + node mean + MLP head. 256-thread blocks (8 warps) sharing
// one copy of the weights; dynamic smem ~56 KB; 3 blocks/SM target.
#define P2_WARPS 8
#define GESTRIDE 33
// dynamic smem layout (floats)
#define S_WR1   0
#define S_WR2   (S_WR1 + D_IN*64)              // 3392
#define S_GE    (S_WR2 + 64*H)                 // +2048
#define S_BR1   (S_GE  + P2_WARPS*32*GESTRIDE) // +8448
#define S_BR2   (S_BR1 + 64)
#define S_WR3   (S_BR2 + 32)
#define S_AS    (S_WR3 + 32)
#define S_MISC  (S_AS + 18)
#define P2_FLOATS (S_MISC + 2)

__global__ __launch_bounds__(256, 3) void pass2_kernel(
    const float* __restrict__ x_raw,   // [B,17]
    const float* __restrict__ x_cov,   // [B,3]
    const float* __restrict__ age,     // [B,1]
    const float* __restrict__ Wr1,     // [53,64]
    const float* __restrict__ br1,     // [64]
    const float* __restrict__ Wr2,     // [64,32]
    const float* __restrict__ br2,     // [32]
    const float* __restrict__ Wr3,     // [32,1]
    const float* __restrict__ br3,     // [1]
    float* __restrict__ out)           // [B,1]
{
    extern __shared__ float sm2[];
    float* Wr1s = sm2 + S_WR1;
    float* Wr2s = sm2 + S_WR2;
    float* geS  = sm2 + S_GE;
    float* br1s = sm2 + S_BR1;
    float* br2s = sm2 + S_BR2;
    float* wr3s = sm2 + S_WR3;
    float* As_  = sm2 + S_AS;
    float* misc = sm2 + S_MISC;

    const int tid = threadIdx.x;
    for (int i = tid; i < D_IN * 64; i += 256) Wr1s[i] = Wr1[i];
    for (int i = tid; i < 64 * H;   i += 256) Wr2s[i] = Wr2[i];
    if (tid < 64) br1s[tid] = br1[tid];
    if (tid < 32) { br2s[tid] = br2[tid]; wr3s[tid] = Wr3[tid]; }
    if (tid < NN) As_[tid] = gA[tid];
    if (tid == 0) { misc[0] = gCbar; misc[1] = br3[0]; }
    __syncthreads();

    const int lane = tid & 31;
    const int w    = tid >> 5;
    float* ge = geS + w * (32 * GESTRIDE);
    const long base = ((long)blockIdx.x * P2_WARPS + w) * 32;

    float As_r[NN];
    #pragma unroll
    for (int n = 0; n < NN; n++) As_r[n] = As_[n];
    const float cbar = misc[0];

    // ---- Phase A: graph_emb (BN-folded) for this warp's 32 samples ----
    #pragma unroll 1
    for (int s2 = 0; s2 < 32; s2++) {
        const __half* hp = gH2h + (base + s2) * (NN * H);
        float g = cbar;
        #pragma unroll
        for (int n = 0; n < NN; n++)
            g += As_r[n] * __half2float(hp[n * H + lane]);
        ge[s2 * GESTRIDE + lane] = g;
    }
    __syncwarp();

    // ---- Phase B: lane = sample ----
    const long b = base + lane;
    const float* cl = ge + lane * GESTRIDE;

    float xr[21];
    {
        const float* xrp = x_raw + b * NN;
        #pragma unroll
        for (int i = 0; i < NN; i++) xr[i] = xrp[i];
        const float* xcp = x_cov + b * 3;
        xr[17] = xcp[0]; xr[18] = xcp[1]; xr[19] = xcp[2];
        xr[20] = age[b];
    }

    ull z2a[16];
    const ull* b2u = reinterpret_cast<const ull*>(br2s);
    #pragma unroll
    for (int j = 0; j < 16; j++) z2a[j] = b2u[j];

    #pragma unroll
    for (int c = 0; c < 4; c++) {
        ull za[8];
        const ull* b1u = reinterpret_cast<const ull*>(br1s + 16 * c);
        #pragma unroll
        for (int j = 0; j < 8; j++) za[j] = b1u[j];

        #pragma unroll 1
        for (int p = 0; p < 16; p++) {
            float f0 = cl[2 * p];
            float f1 = cl[2 * p + 1];
            ull ca = pk2(f0, f0);
            ull cb = pk2(f1, f1);
            const ulonglong2* wa = reinterpret_cast<const ulonglong2*>(&Wr1s[(2 * p) * 64 + 16 * c]);
            const ulonglong2* wb = reinterpret_cast<const ulonglong2*>(&Wr1s[(2 * p + 1) * 64 + 16 * c]);
            #pragma unroll
            for (int q = 0; q < 4; q++) {
                ulonglong2 va = wa[q];
                ffma2(za[2 * q],     ca, va.x);
                ffma2(za[2 * q + 1], ca, va.y);
            }
            #pragma unroll
            for (int q = 0; q < 4; q++) {
                ulonglong2 vb = wb[q];
                ffma2(za[2 * q],     cb, vb.x);
                ffma2(za[2 * q + 1], cb, vb.y);
            }
        }
        #pragma unroll 1
        for (int p = 0; p < 10; p++) {
            float f0 = xr[2 * p];
            float f1 = xr[2 * p + 1];
            ull ca = pk2(f0, f0);
            ull cb = pk2(f1, f1);
            const ulonglong2* wa = reinterpret_cast<const ulonglong2*>(&Wr1s[(32 + 2 * p) * 64 + 16 * c]);
            const ulonglong2* wb = reinterpret_cast<const ulonglong2*>(&Wr1s[(33 + 2 * p) * 64 + 16 * c]);
            #pragma unroll
            for (int q = 0; q < 4; q++) {
                ulonglong2 va = wa[q];
                ffma2(za[2 * q],     ca, va.x);
                ffma2(za[2 * q + 1], ca, va.y);
            }
            #pragma unroll
            for (int q = 0; q < 4; q++) {
                ulonglong2 vb = wb[q];
                ffma2(za[2 * q],     cb, vb.x);
                ffma2(za[2 * q + 1], cb, vb.y);
            }
        }
        {
            float ci = xr[20];
            ull c2 = pk2(ci, ci);
            const ulonglong2* wv = reinterpret_cast<const ulonglong2*>(&Wr1s[52 * 64 + 16 * c]);
            #pragma unroll
            for (int q = 0; q < 4; q++) {
                ulonglong2 v = wv[q];
                ffma2(za[2 * q],     c2, v.x);
                ffma2(za[2 * q + 1], c2, v.y);
            }
        }

        #pragma unroll
        for (int j = 0; j < 8; j++) {
            float r0, r1; upk2(za[j], r0, r1);
            r0 = fmaxf(r0, 0.f); r1 = fmaxf(r1, 0.f);
            int k0 = 16 * c + 2 * j;
            ull ca = pk2(r0, r0);
            ull cb = pk2(r1, r1);
            const ulonglong2* wa = reinterpret_cast<const ulonglong2*>(&Wr2s[k0 * 32]);
            const ulonglong2* wb = reinterpret_cast<const ulonglong2*>(&Wr2s[(k0 + 1) * 32]);
            #pragma unroll
            for (int q = 0; q < 8; q++) {
                ulonglong2 va = wa[q];
                ffma2(z2a[2 * q],     ca, va.x);
                ffma2(z2a[2 * q + 1], ca, va.y);
            }
            #pragma unroll
            for (int q = 0; q < 8; q++) {
                ulonglong2 vb = wb[q];
                ffma2(z2a[2 * q],     cb, vb.x);
                ffma2(z2a[2 * q + 1], cb, vb.y);
            }
        }
    }

    float acc = misc[1];
    #pragma unroll
    for (int j = 0; j < 16; j++) {
        float lo, hi; upk2(z2a[j], lo, hi);
        acc += fmaxf(lo, 0.f) * wr3s[2 * j];
        acc += fmaxf(hi, 0.f) * wr3s[2 * j + 1];
    }
    out[b] = 1.f / (1.f + __expf(-acc));
}

// ---------------------------------------------------------------------------
extern "C" void kernel_launch(void* const* d_in, const int* in_sizes, int n_in,
                              void* d_out, int out_size)
{
    const float* x_str = (const float*)d_in[0];
    const float* x_raw = (const float*)d_in[1];
    const float* adj   = (const float*)d_in[2];
    const float* x_cov = (const float*)d_in[3];
    const float* age   = (const float*)d_in[4];
    const float* W1    = (const float*)d_in[5];
    const float* b1    = (const float*)d_in[6];
    const float* W2    = (const float*)d_in[7];
    const float* b2    = (const float*)d_in[8];
    const float* gamma = (const float*)d_in[9];
    const float* beta  = (const float*)d_in[10];
    const float* Wr1   = (const float*)d_in[11];
    const float* br1   = (const float*)d_in[12];
    const float* Wr2   = (const float*)d_in[13];
    const float* br2   = (const float*)d_in[14];
    const float* Wr3   = (const float*)d_in[15];
    const float* br3   = (const float*)d_in[16];

    const int blocks1 = B_TOT / (WPB * SPW);          // 2048
    const int blocks2 = B_TOT / (P2_WARPS * 32);      // 512
    const int smem1   = P1_FLOATS * 4;                // ~89 KB
    const int smem2   = P2_FLOATS * 4;                // ~56.2 KB

    static int attr_done = 0;
    if (!attr_done) {
        cudaFuncSetAttribute(pass1_kernel,
                             cudaFuncAttributeMaxDynamicSharedMemorySize, smem1);
        cudaFuncSetAttribute(pass2_kernel,
                             cudaFuncAttributeMaxDynamicSharedMemorySize, smem2);
        attr_done = 1;
    }

    pass1_kernel<<<blocks1, 256, smem1>>>(x_str, adj, W1, b1, W2, b2);
    stats_kernel<<<2048, 272>>>();
    finalize_kernel<<<1, 32>>>(gamma, beta);
    pass2_kernel<<<blocks2, 256, smem2>>>(x_raw, x_cov, age,
                                          Wr1, br1, Wr2, br2, Wr3, br3,
                                          (float*)d_out);
}